// round 13
// baseline (speedup 1.0000x reference)
#include <cuda_runtime.h>
#include <cuda_fp16.h>
#include <cstdint>

// ---------------- problem constants ----------------
constexpr int AEVD = 384;
constexpr int H1D  = 160;
constexpr int H2D  = 128;
constexpr int H3D  = 96;
constexpr int MT   = 128;    // atoms per CTA

// transposed RN-fp16 weights: W1T[4][160][384], W2T[4][128][160], W3T[4][96][128]
__device__ __half g_WTh[376832];
__device__ float g_partials[4096];
__device__ unsigned int g_ticket;   // zero-init; reset by last CTA each launch
constexpr int W1T_OFF = 0;
constexpr int W2T_OFF = 245760;
constexpr int W3T_OFF = 327680;

// ---------------- SMEM layout (bytes) ----------------
// ALL row strides must be multiples of 16 (ldmatrix row alignment) and ≡ 16/80
// (mod 128) for conflict-free 8-row access groups. (R12 failed on 328%16=8.)
constexpr int ACH   = 80;      // A chunk row stride (32 fp16 = 64B + 16 pad)
constexpr int WCH   = 80;      // W chunk row stride (32 fp16 + pad)
constexpr int LD1B  = 336;     // h1 row stride (168 fp16); 336%16=0, 336%128=80
constexpr int LD2B  = 272;     // h2 row stride (136 fp16); 272%16=0, 272%128=16
constexpr int OFF_H1   = 0;        // 128*336 = 43008
constexpr int OFF_W0   = 43008;    // 160*80 = 12800
constexpr int OFF_W1   = 55808;    // end 68608
constexpr int OFF_A0   = 68608;    // 128*80 = 10240
constexpr int OFF_A1   = 78848;    // end 89088
constexpr int OFF_H2   = OFF_A0;   // overlay: A bufs dead after L1; h2 = 128*272 = 34816 -> [68608,103424)
constexpr int OFF_SIDX = 103424;   // 128 int
constexpr int OFF_PD   = 103936;   // 256 f
constexpr int OFF_SRED = 104960;   // 8 f
constexpr int SMEM_DYN = 105088;   // x2 CTAs ≈ 210KB < 228KB/SM

// ---------------- helpers ----------------
__device__ __forceinline__ uint32_t smem_u32(const void* p) {
    uint32_t a;
    asm("{ .reg .u64 t; cvta.to.shared.u64 t, %1; cvt.u32.u64 %0, t; }" : "=r"(a) : "l"(p));
    return a;
}
__device__ __forceinline__ float celu_f(float x) {
    return x > 0.0f ? x : 0.1f * (expf(x * 10.0f) - 1.0f);
}
// pack (lo, hi) -> f16x2, RN (first asm source = high half)
__device__ __forceinline__ uint32_t pack_f16(float lo, float hi) {
    uint32_t r;
    asm("cvt.rn.f16x2.f32 %0, %1, %2;" : "=r"(r) : "f"(hi), "f"(lo));
    return r;
}
__device__ __forceinline__ void cp_async16(uint32_t dst, const void* src) {
    asm volatile("cp.async.cg.shared.global [%0], [%1], 16;"
                 :: "r"(dst), "l"(src) : "memory");
}
__device__ __forceinline__ void cp_commit() { asm volatile("cp.async.commit_group;" ::: "memory"); }
__device__ __forceinline__ void cp_wait1()  { asm volatile("cp.async.wait_group 1;" ::: "memory"); }
__device__ __forceinline__ void cp_wait0()  { asm volatile("cp.async.wait_group 0;" ::: "memory"); }

__device__ __forceinline__ void ldsm_x4(uint32_t& r0, uint32_t& r1, uint32_t& r2, uint32_t& r3,
                                        uint32_t addr) {
    asm volatile("ldmatrix.sync.aligned.m8n8.x4.shared.b16 {%0,%1,%2,%3}, [%4];"
                 : "=r"(r0), "=r"(r1), "=r"(r2), "=r"(r3) : "r"(addr));
}

// D += A(16x16 fp16 row) * B(16x8 fp16 col), fp32 accum
__device__ __forceinline__ void mma16(float* d, const uint32_t* a, uint32_t b0, uint32_t b1) {
    asm volatile(
        "mma.sync.aligned.m16n8k16.row.col.f32.f16.f16.f32 "
        "{%0,%1,%2,%3}, {%4,%5,%6,%7}, {%8,%9}, {%0,%1,%2,%3};"
        : "+f"(d[0]), "+f"(d[1]), "+f"(d[2]), "+f"(d[3])
        : "r"(a[0]), "r"(a[1]), "r"(a[2]), "r"(a[3]), "r"(b0), "r"(b1));
}

// ---------------- staging of one 32-k chunk ----------------
// GATHER: LDG fp32 rows (scattered atoms) -> cvt RN fp16 -> STS.128 (identical
// numerics to converting at fragment time, but done once instead of per-warp).
// W: cp.async fp16 (already converted in prep).
template<int K, bool GATHER>
__device__ __forceinline__ void stage_chunk(
    const float* __restrict__ gA, const int* __restrict__ sidx,
    const __half* __restrict__ gWT, int N, int c,
    char* ab, char* wb, int tid)
{
    const int k0 = c * 32;
    float4 v0, v1, v2, v3;
    int r = 0, h8 = 0;
    if (GATHER) {
        r = tid & 127; h8 = tid >> 7;
        int atom = sidx[r];
        v0 = v1 = v2 = v3 = make_float4(0.f, 0.f, 0.f, 0.f);
        if (atom >= 0) {
            const float4* src = reinterpret_cast<const float4*>(
                gA + (size_t)atom * AEVD + k0 + h8 * 16);
            v0 = src[0]; v1 = src[1]; v2 = src[2]; v3 = src[3];
        }
    }
    // W cp.asyncs issued while the A LDGs are in flight
    uint32_t wbs = smem_u32(wb);
    for (int i = tid; i < N * 4; i += 256) {
        int n = i >> 2, s3 = i & 3;
        cp_async16(wbs + n * WCH + s3 * 16, gWT + (size_t)n * K + k0 + s3 * 8);
    }
    cp_commit();
    if (GATHER) {
        uint4 lo, hi;
        lo.x = pack_f16(v0.x, v0.y); lo.y = pack_f16(v0.z, v0.w);
        lo.z = pack_f16(v1.x, v1.y); lo.w = pack_f16(v1.z, v1.w);
        hi.x = pack_f16(v2.x, v2.y); hi.y = pack_f16(v2.z, v2.w);
        hi.z = pack_f16(v3.x, v3.y); hi.w = pack_f16(v3.z, v3.w);
        char* dst = ab + r * ACH + h8 * 32;
        *reinterpret_cast<uint4*>(dst)      = lo;
        *reinterpret_cast<uint4*>(dst + 16) = hi;
    }
}

// ---------------- one MLP layer (fp16 mma, fp32 accum, ldmatrix feeds) -----
// Warp w: m-quarter mh=w&3 (2 m16 tiles), n-half nh=w>>2 (TN = N/16 n8-tiles).
template<int K, int N, bool GATHER, bool FINAL>
__device__ __forceinline__ void layer(
    const float* __restrict__ gA, const int* __restrict__ sidx,
    const char* __restrict__ hA, int lda,            // resident fp16 A (byte stride)
    const __half* __restrict__ gWT,
    const float* __restrict__ bias, const float* __restrict__ w4,
    char* __restrict__ smem, char* __restrict__ hout, int ldo,
    float* __restrict__ pd)
{
    constexpr int NC = K / 32;
    constexpr int NH = N / 2;
    constexpr int TN = NH / 8;       // 10, 8, 6
    constexpr int TB = TN / 2;       // 5, 4, 3
    const int tid  = threadIdx.x;
    const int lane = tid & 31, w = tid >> 5;
    const int mh = w & 3, nh = w >> 2;
    const int g = lane >> 2, tig = lane & 3;
    const int lrow = lane & 7, lsub = lane >> 3;

    // ldmatrix lane address offsets
    // B: m0=n(+0..7) k-lo, m1=k-hi, m2=n(+8..15) k-lo, m3=k-hi
    const uint32_t b_lane = (uint32_t)((nh * NH + lrow + (lane >> 4) * 8) * WCH
                                       + ((lane >> 3) & 1) * 16);
    // A: m0=rows+0..7 k-lo, m1=rows+8..15 k-lo, m2=rows+0..7 k-hi, m3=rows+8..15 k-hi
    uint32_t a_off[2];
    {
        const int stride = GATHER ? ACH : lda;
#pragma unroll
        for (int mt = 0; mt < 2; mt++)
            a_off[mt] = (uint32_t)((mh * 32 + mt * 16 + lrow + (lsub & 1) * 8) * stride
                                   + (lsub >> 1) * 16);
    }
    uint32_t a_base[2];   // per c&1 buffer bases (GATHER) or resident base (dup)
    if (GATHER) {
        a_base[0] = smem_u32(smem + OFF_A0);
        a_base[1] = smem_u32(smem + OFF_A1);
    } else {
        a_base[0] = a_base[1] = smem_u32(hA);
    }

    float acc[2][TN][4];
#pragma unroll
    for (int mt = 0; mt < 2; mt++)
#pragma unroll
        for (int t = 0; t < TN; t++)
#pragma unroll
            for (int j = 0; j < 4; j++) acc[mt][t][j] = 0.0f;

    char* abufs[2] = { smem + OFF_A0, smem + OFF_A1 };
    char* wbufs[2] = { smem + OFF_W0, smem + OFF_W1 };

    stage_chunk<K, GATHER>(gA, sidx, gWT, N, 0, abufs[0], wbufs[0], tid);

    for (int c = 0; c < NC; c++) {
        if (c + 1 < NC) {
            stage_chunk<K, GATHER>(gA, sidx, gWT, N, c + 1,
                                   abufs[(c + 1) & 1], wbufs[(c + 1) & 1], tid);
            cp_wait1();
        } else {
            cp_wait0();
        }
        __syncthreads();

        const uint32_t wb_u = smem_u32(wbufs[c & 1]) + b_lane;
        const uint32_t ab_u = GATHER ? a_base[c & 1] : (a_base[0] + c * 64);

#pragma unroll
        for (int h = 0; h < 2; h++) {        // two k16 halves per 32-chunk
            uint32_t a[2][4];
#pragma unroll
            for (int mt = 0; mt < 2; mt++)
                ldsm_x4(a[mt][0], a[mt][1], a[mt][2], a[mt][3],
                        ab_u + a_off[mt] + h * 32);
#pragma unroll
            for (int tb = 0; tb < TB; tb++) {
                uint32_t b0, b1, b2, b3;
                ldsm_x4(b0, b1, b2, b3, wb_u + tb * (16 * WCH) + h * 32);
                mma16(acc[0][2 * tb],     a[0], b0, b1);
                mma16(acc[1][2 * tb],     a[1], b0, b1);
                mma16(acc[0][2 * tb + 1], a[0], b2, b3);
                mma16(acc[1][2 * tb + 1], a[1], b2, b3);
            }
        }
        __syncthreads();   // protect buf c&1 before restage at c+2
    }

    // ---- epilogue ----
    if (FINAL) {
#pragma unroll
        for (int mt = 0; mt < 2; mt++) {
            float slo = 0.0f, shi = 0.0f;
#pragma unroll
            for (int t = 0; t < TN; t++) {
                int col = nh * NH + t * 8 + 2 * tig;
                float b0 = __ldg(bias + col), b1 = __ldg(bias + col + 1);
                float w0 = __ldg(w4 + col),   w1 = __ldg(w4 + col + 1);
                slo += celu_f(acc[mt][t][0] + b0) * w0 + celu_f(acc[mt][t][1] + b1) * w1;
                shi += celu_f(acc[mt][t][2] + b0) * w0 + celu_f(acc[mt][t][3] + b1) * w1;
            }
#pragma unroll
            for (int o = 1; o <= 2; o <<= 1) {
                slo += __shfl_xor_sync(0xffffffffu, slo, o);
                shi += __shfl_xor_sync(0xffffffffu, shi, o);
            }
            if (tig == 0) {
                int r = mh * 32 + mt * 16 + g;
                pd[r * 2 + nh]       = slo;
                pd[(r + 8) * 2 + nh] = shi;
            }
        }
    } else {
#pragma unroll
        for (int mt = 0; mt < 2; mt++) {
            int r = mh * 32 + mt * 16 + g;
#pragma unroll
            for (int t = 0; t < TN; t++) {
                int col = nh * NH + t * 8 + 2 * tig;
                float b0 = __ldg(bias + col), b1 = __ldg(bias + col + 1);
                uint32_t lo = pack_f16(celu_f(acc[mt][t][0] + b0), celu_f(acc[mt][t][1] + b1));
                uint32_t hi = pack_f16(celu_f(acc[mt][t][2] + b0), celu_f(acc[mt][t][3] + b1));
                *reinterpret_cast<uint32_t*>(hout + r * ldo + col * 2)       = lo;
                *reinterpret_cast<uint32_t*>(hout + (r + 8) * ldo + col * 2) = hi;
            }
        }
    }
}

// ---------------- main kernel (with fused final reduction) ----------------
__global__ void __launch_bounds__(256, 2)
ani_kernel(const float* __restrict__ aev,
           const float* __restrict__ b1, const float* __restrict__ b2,
           const float* __restrict__ b3,
           const float* __restrict__ W4, const float* __restrict__ b4,
           const int* __restrict__ idx0, const int* __restrict__ idx1,
           const int* __restrict__ idx2, const int* __restrict__ idx3,
           int4 cnts, float* __restrict__ out)
{
    extern __shared__ __align__(128) char smem[];
    __shared__ bool is_last;
    __shared__ double sd[256];

    const int s    = blockIdx.y;
    const int tile = blockIdx.x;
    const int cnt  = (&cnts.x)[s];
    const int flat = s * gridDim.x + tile;
    const int base = tile * MT;
    const int tid  = threadIdx.x;
    const bool active = (base < cnt);

    if (active) {
        int*   sidx = (int*)(smem + OFF_SIDX);
        float* pd   = (float*)(smem + OFF_PD);
        float* sred = (float*)(smem + OFF_SRED);

        const int* idx = (s == 0) ? idx0 : (s == 1) ? idx1 : (s == 2) ? idx2 : idx3;
        if (tid < MT) sidx[tid] = (base + tid < cnt) ? idx[base + tid] : -1;
        __syncthreads();

        // layer 1: gather aev [128x384] @ W1 -> h1 fp16 [128x160]
        layer<AEVD, H1D, true, false>(aev, sidx, nullptr, 0,
                                      g_WTh + W1T_OFF + (size_t)s * H1D * AEVD,
                                      b1 + s * H1D, nullptr,
                                      smem, smem + OFF_H1, LD1B, nullptr);
        __syncthreads();
        // layer 2: h1 @ W2 -> h2 fp16 [128x128]
        layer<H1D, H2D, false, false>(nullptr, nullptr, smem + OFF_H1, LD1B,
                                      g_WTh + W2T_OFF + (size_t)s * H2D * H1D,
                                      b2 + s * H2D, nullptr,
                                      smem, smem + OFF_H2, LD2B, nullptr);
        __syncthreads();
        // layer 3: h2 @ W3 -> celu -> fused dot W4 -> pd
        layer<H2D, H3D, false, true>(nullptr, nullptr, smem + OFF_H2, LD2B,
                                     g_WTh + W3T_OFF + (size_t)s * H3D * H2D,
                                     b3 + s * H3D, W4 + s * H3D,
                                     smem, nullptr, 0, pd);
        __syncthreads();

        // combine halves, mask pads, block reduce
        float e = 0.0f;
        if (tid < MT) {
            if (base + tid < cnt) e = pd[tid * 2] + pd[tid * 2 + 1] + __ldg(b4 + s);
#pragma unroll
            for (int o = 16; o > 0; o >>= 1) e += __shfl_down_sync(0xffffffffu, e, o);
            if ((tid & 31) == 0) sred[tid >> 5] = e;
        }
        __syncthreads();
        if (tid == 0) g_partials[flat] = sred[0] + sred[1] + sred[2] + sred[3];
    } else {
        if (tid == 0) g_partials[flat] = 0.0f;
    }

    // ---- last CTA performs the deterministic global reduction ----
    __threadfence();
    if (tid == 0) {
        unsigned int t = atomicAdd(&g_ticket, 1u);
        is_last = (t == gridDim.x * gridDim.y - 1);
    }
    __syncthreads();
    if (is_last) {
        const int n = gridDim.x * gridDim.y;
        double acc = 0.0;
        for (int i = tid; i < n; i += 256) acc += (double)g_partials[i];
        sd[tid] = acc;
        __syncthreads();
#pragma unroll
        for (int o = 128; o > 0; o >>= 1) {
            if (tid < o) sd[tid] += sd[tid + o];
            __syncthreads();
        }
        if (tid == 0) {
            out[0] = (float)sd[0];
            g_ticket = 0;          // reset for next graph replay
        }
    }
}

// ---------------- weight transpose + RN fp16 (coalesced writes) -----------
__global__ void __launch_bounds__(256)
prep_kernel(const float* __restrict__ W1, const float* __restrict__ W2,
            const float* __restrict__ W3)
{
    int j = blockIdx.x * 256 + threadIdx.x;
    if (j < 4 * H1D * AEVD) {                  // W1T[sp][n][k] <- W1[sp][k][n]
        int sp = j / (H1D * AEVD), r = j % (H1D * AEVD);
        int n = r / AEVD, k = r % AEVD;
        g_WTh[W1T_OFF + j] = __float2half_rn(W1[(size_t)sp * AEVD * H1D + k * H1D + n]);
    }
    if (j < 4 * H2D * H1D) {
        int sp = j / (H2D * H1D), r = j % (H2D * H1D);
        int n = r / H1D, k = r % H1D;
        g_WTh[W2T_OFF + j] = __float2half_rn(W2[(size_t)sp * H1D * H2D + k * H2D + n]);
    }
    if (j < 4 * H3D * H2D) {
        int sp = j / (H3D * H2D), r = j % (H3D * H2D);
        int n = r / H2D, k = r % H2D;
        g_WTh[W3T_OFF + j] = __float2half_rn(W3[(size_t)sp * H2D * H3D + k * H3D + n]);
    }
}

extern "C" void kernel_launch(void* const* d_in, const int* in_sizes, int n_in,
                              void* d_out, int out_size)
{
    const float* aev = (const float*)d_in[0];
    const float* W1  = (const float*)d_in[1];
    const float* b1  = (const float*)d_in[2];
    const float* W2  = (const float*)d_in[3];
    const float* b2  = (const float*)d_in[4];
    const float* W3  = (const float*)d_in[5];
    const float* b3  = (const float*)d_in[6];
    const float* W4  = (const float*)d_in[7];
    const float* b4  = (const float*)d_in[8];
    const int* idx0  = (const int*)d_in[9];
    const int* idx1  = (const int*)d_in[10];
    const int* idx2  = (const int*)d_in[11];
    const int* idx3  = (const int*)d_in[12];

    int4 cnts;
    cnts.x = in_sizes[9];  cnts.y = in_sizes[10];
    cnts.z = in_sizes[11]; cnts.w = in_sizes[12];
    int maxc = cnts.x;
    if (cnts.y > maxc) maxc = cnts.y;
    if (cnts.z > maxc) maxc = cnts.z;
    if (cnts.w > maxc) maxc = cnts.w;
    int tiles = (maxc + MT - 1) / MT;

    prep_kernel<<<(4 * H1D * AEVD + 255) / 256, 256>>>(W1, W2, W3);

    cudaFuncSetAttribute(ani_kernel, cudaFuncAttributeMaxDynamicSharedMemorySize, SMEM_DYN);
    dim3 grid(tiles, 4);
    ani_kernel<<<grid, 256, SMEM_DYN>>>(aev, b1, b2, b3, W4, b4,
                                        idx0, idx1, idx2, idx3, cnts, (float*)d_out);
}

// round 16
// speedup vs baseline: 1.2257x; 1.2257x over previous
#include <cuda_runtime.h>
#include <cuda_fp16.h>
#include <cstdint>

// ---------------- problem constants ----------------
constexpr int AEVD = 384;
constexpr int H1D  = 160;
constexpr int H2D  = 128;
constexpr int H3D  = 96;
constexpr int MT   = 64;     // atoms per CTA (3 CTAs/SM)

// transposed RN-fp16 weights: W1T[4][160][384], W2T[4][128][160], W3T[4][96][128]
__device__ __half g_WTh[376832];
__device__ float g_partials[4096];
__device__ unsigned int g_ticket;   // zero-init; reset by last CTA each launch
constexpr int W1T_OFF = 0;
constexpr int W2T_OFF = 245760;
constexpr int W3T_OFF = 327680;

// ---------------- SMEM layout (bytes) ----------------
// row strides: multiple of 16 (ldmatrix) and ≡16/80 (mod 128) → conflict-free
constexpr int SCH   = 144;     // A chunk row stride (32 fp32 + pad)
constexpr int WCH   = 80;      // W chunk row stride (32 fp16 + pad)
constexpr int LD1B  = 336;     // h1 row stride (168 fp16)
constexpr int LD2B  = 272;     // h2 row stride (136 fp16)
constexpr int OFF_H1   = 0;        // 64*336 = 21504
constexpr int OFF_W0   = 21504;    // 160*80 = 12800
constexpr int OFF_W1   = 34304;    // end 47104
constexpr int OFF_A0   = 47104;    // 64*144 = 9216
constexpr int OFF_A1   = 56320;    // end 65536
constexpr int OFF_H2   = OFF_A0;   // overlay: 64*272 = 17408 <= 18432 A-buf area
constexpr int OFF_SIDX = 65536;    // 64 int
constexpr int OFF_PD   = 65792;    // 128 f
constexpr int OFF_SRED = 66304;    // 8 f
constexpr int SMEM_DYN = 66560;    // x3 CTAs ≈ 200KB < 228KB/SM

// ---------------- helpers ----------------
__device__ __forceinline__ uint32_t smem_u32(const void* p) {
    uint32_t a;
    asm("{ .reg .u64 t; cvta.to.shared.u64 t, %1; cvt.u32.u64 %0, t; }" : "=r"(a) : "l"(p));
    return a;
}
__device__ __forceinline__ float celu_f(float x) {
    return x > 0.0f ? x : 0.1f * (expf(x * 10.0f) - 1.0f);
}
// pack (lo, hi) -> f16x2, RN (first asm source = high half)
__device__ __forceinline__ uint32_t pack_f16(float lo, float hi) {
    uint32_t r;
    asm("cvt.rn.f16x2.f32 %0, %1, %2;" : "=r"(r) : "f"(hi), "f"(lo));
    return r;
}
__device__ __forceinline__ void cp_async16(uint32_t dst, const void* src, int nbytes) {
    asm volatile("cp.async.cg.shared.global [%0], [%1], 16, %2;"
                 :: "r"(dst), "l"(src), "r"(nbytes) : "memory");
}
__device__ __forceinline__ void cp_commit() { asm volatile("cp.async.commit_group;" ::: "memory"); }
__device__ __forceinline__ void cp_wait0()  { asm volatile("cp.async.wait_group 0;" ::: "memory"); }

__device__ __forceinline__ void ldsm_x4(uint32_t& r0, uint32_t& r1, uint32_t& r2, uint32_t& r3,
                                        uint32_t addr) {
    asm volatile("ldmatrix.sync.aligned.m8n8.x4.shared.b16 {%0,%1,%2,%3}, [%4];"
                 : "=r"(r0), "=r"(r1), "=r"(r2), "=r"(r3) : "r"(addr));
}

// D += A(16x16 fp16 row) * B(16x8 fp16 col), fp32 accum
__device__ __forceinline__ void mma16(float* d, const uint32_t* a, uint32_t b0, uint32_t b1) {
    asm volatile(
        "mma.sync.aligned.m16n8k16.row.col.f32.f16.f16.f32 "
        "{%0,%1,%2,%3}, {%4,%5,%6,%7}, {%8,%9}, {%0,%1,%2,%3};"
        : "+f"(d[0]), "+f"(d[1]), "+f"(d[2]), "+f"(d[3])
        : "r"(a[0]), "r"(a[1]), "r"(a[2]), "r"(a[3]), "r"(b0), "r"(b1));
}

// ---------------- staging of one 32-k chunk (all cp.async) ----------------
template<int K, bool GATHER>
__device__ __forceinline__ void stage_chunk(
    const float* __restrict__ gA, const int* __restrict__ sidx,
    const __half* __restrict__ gWT, int N, int c, char* ab, char* wb, int tid)
{
    const int k0 = c * 32;
    if (GATHER) {
        uint32_t abs_ = smem_u32(ab);
        // 64 rows x 8 segs of 16B (fp32)
        for (int i = tid; i < MT * 8; i += 256) {
            int r = i >> 3, s7 = i & 7;
            int atom = sidx[r];
            const float* src = gA + (atom < 0 ? 0 : ((size_t)atom * AEVD + k0 + s7 * 4));
            cp_async16(abs_ + r * SCH + s7 * 16, src, atom < 0 ? 0 : 16);
        }
    }
    uint32_t wbs = smem_u32(wb);
    for (int i = tid; i < N * 4; i += 256) {
        int n = i >> 2, s3 = i & 3;
        cp_async16(wbs + n * WCH + s3 * 16, gWT + (size_t)n * K + k0 + s3 * 8, 16);
    }
    cp_commit();
}

// ---------------- one MLP layer (fp16 mma, fp32 accum) ----------------
// Warp w: m-tile mt4=w&3 (one m16 tile of 64 rows), n-half nh=w>>2.
// Single barrier per chunk: wait -> bar -> issue stage(c+1) -> compute(c).
template<int K, int N, bool GATHER, bool FINAL>
__device__ __forceinline__ void layer(
    const float* __restrict__ gA, const int* __restrict__ sidx,
    const char* __restrict__ hA, int lda,            // resident fp16 A (byte stride)
    const __half* __restrict__ gWT,
    const float* __restrict__ bias, const float* __restrict__ w4,
    char* __restrict__ smem, char* __restrict__ hout, int ldo,
    float* __restrict__ pd)
{
    constexpr int NC = K / 32;
    constexpr int NH = N / 2;
    constexpr int TN = NH / 8;       // 10, 8, 6
    constexpr int TB = TN / 2;       // 5, 4, 3
    const int tid  = threadIdx.x;
    const int lane = tid & 31, w = tid >> 5;
    const int mt4 = w & 3, nh = w >> 2;
    const int g = lane >> 2, tig = lane & 3;
    const int lrow = lane & 7, lsub = lane >> 3;

    // B ldmatrix lane address: m0/m1 = n(+0..7) k-lo/k-hi, m2/m3 = n(+8..15)
    const uint32_t b_lane = (uint32_t)((nh * NH + lrow + (lane >> 4) * 8) * WCH
                                       + ((lane >> 3) & 1) * 16);
    // resident A ldmatrix: m0=rows+0..7 k-lo, m1=rows+8..15 k-lo, m2/m3 = k-hi
    uint32_t a_off = 0, a_base = 0;
    if (!GATHER) {
        a_base = smem_u32(hA);
        a_off = (uint32_t)((mt4 * 16 + lrow + (lsub & 1) * 8) * lda + (lsub >> 1) * 16);
    }
    const int r0 = mt4 * 16 + g;     // GATHER fragment row

    float acc[TN][4];
#pragma unroll
    for (int t = 0; t < TN; t++)
#pragma unroll
        for (int j = 0; j < 4; j++) acc[t][j] = 0.0f;

    char* abufs[2] = { smem + OFF_A0, smem + OFF_A1 };
    char* wbufs[2] = { smem + OFF_W0, smem + OFF_W1 };

    stage_chunk<K, GATHER>(gA, sidx, gWT, N, 0, abufs[0], wbufs[0], tid);

    for (int c = 0; c < NC; c++) {
        cp_wait0();          // this thread's cp.asyncs for chunk c done
        __syncthreads();     // all threads' data for c visible; compute(c-1) finished
        if (c + 1 < NC)      // stage next chunk; overlaps with compute(c) below
            stage_chunk<K, GATHER>(gA, sidx, gWT, N, c + 1,
                                   abufs[(c + 1) & 1], wbufs[(c + 1) & 1], tid);

        const uint32_t wb_u = smem_u32(wbufs[c & 1]) + b_lane;
        const char* ab = abufs[c & 1];

#pragma unroll
        for (int h = 0; h < 2; h++) {        // two k16 halves per 32-chunk
            const int kc = h * 16;
            uint32_t a[4];
            if (GATHER) {                    // fp32 staged -> RN fp16 fragments
                const char* ar = ab + r0 * SCH + (kc + 2 * tig) * 4;
                float2 p0 = *reinterpret_cast<const float2*>(ar);
                float2 p1 = *reinterpret_cast<const float2*>(ar + 8 * SCH);
                float2 p2 = *reinterpret_cast<const float2*>(ar + 32);
                float2 p3 = *reinterpret_cast<const float2*>(ar + 8 * SCH + 32);
                a[0] = pack_f16(p0.x, p0.y);
                a[1] = pack_f16(p1.x, p1.y);
                a[2] = pack_f16(p2.x, p2.y);
                a[3] = pack_f16(p3.x, p3.y);
            } else {
                ldsm_x4(a[0], a[1], a[2], a[3], a_base + a_off + c * 64 + h * 32);
            }
#pragma unroll
            for (int tb = 0; tb < TB; tb++) {
                uint32_t b0, b1, b2, b3;
                ldsm_x4(b0, b1, b2, b3, wb_u + tb * (16 * WCH) + h * 32);
                mma16(acc[2 * tb],     a, b0, b1);
                mma16(acc[2 * tb + 1], a, b2, b3);
            }
        }
    }

    // ---- epilogue ----
    if (FINAL) {
        float slo = 0.0f, shi = 0.0f;
#pragma unroll
        for (int t = 0; t < TN; t++) {
            int col = nh * NH + t * 8 + 2 * tig;
            float b0 = __ldg(bias + col), b1 = __ldg(bias + col + 1);
            float w0 = __ldg(w4 + col),   w1 = __ldg(w4 + col + 1);
            slo += celu_f(acc[t][0] + b0) * w0 + celu_f(acc[t][1] + b1) * w1;
            shi += celu_f(acc[t][2] + b0) * w0 + celu_f(acc[t][3] + b1) * w1;
        }
#pragma unroll
        for (int o = 1; o <= 2; o <<= 1) {
            slo += __shfl_xor_sync(0xffffffffu, slo, o);
            shi += __shfl_xor_sync(0xffffffffu, shi, o);
        }
        if (tig == 0) {
            pd[r0 * 2 + nh]       = slo;    // r0 = mt4*16 + g
            pd[(r0 + 8) * 2 + nh] = shi;
        }
    } else {
#pragma unroll
        for (int t = 0; t < TN; t++) {
            int col = nh * NH + t * 8 + 2 * tig;
            float b0 = __ldg(bias + col), b1 = __ldg(bias + col + 1);
            uint32_t lo = pack_f16(celu_f(acc[t][0] + b0), celu_f(acc[t][1] + b1));
            uint32_t hi = pack_f16(celu_f(acc[t][2] + b0), celu_f(acc[t][3] + b1));
            *reinterpret_cast<uint32_t*>(hout + r0 * ldo + col * 2)       = lo;
            *reinterpret_cast<uint32_t*>(hout + (r0 + 8) * ldo + col * 2) = hi;
        }
    }
}

// ---------------- main kernel (with fused final reduction) ----------------
__global__ void __launch_bounds__(256, 3)
ani_kernel(const float* __restrict__ aev,
           const float* __restrict__ b1, const float* __restrict__ b2,
           const float* __restrict__ b3,
           const float* __restrict__ W4, const float* __restrict__ b4,
           const int* __restrict__ idx0, const int* __restrict__ idx1,
           const int* __restrict__ idx2, const int* __restrict__ idx3,
           int4 cnts, float* __restrict__ out)
{
    extern __shared__ __align__(128) char smem[];
    __shared__ bool is_last;
    __shared__ double sd[256];

    const int s    = blockIdx.y;
    const int tile = blockIdx.x;
    const int cnt  = (&cnts.x)[s];
    const int flat = s * gridDim.x + tile;
    const int base = tile * MT;
    const int tid  = threadIdx.x;
    const bool active = (base < cnt);

    if (active) {
        int*   sidx = (int*)(smem + OFF_SIDX);
        float* pd   = (float*)(smem + OFF_PD);
        float* sred = (float*)(smem + OFF_SRED);

        const int* idx = (s == 0) ? idx0 : (s == 1) ? idx1 : (s == 2) ? idx2 : idx3;
        if (tid < MT) sidx[tid] = (base + tid < cnt) ? idx[base + tid] : -1;
        __syncthreads();

        // layer 1: gather aev [64x384] @ W1 -> h1 fp16 [64x160]
        layer<AEVD, H1D, true, false>(aev, sidx, nullptr, 0,
                                      g_WTh + W1T_OFF + (size_t)s * H1D * AEVD,
                                      b1 + s * H1D, nullptr,
                                      smem, smem + OFF_H1, LD1B, nullptr);
        __syncthreads();
        // layer 2: h1 @ W2 -> h2 fp16 [64x128]
        layer<H1D, H2D, false, false>(nullptr, nullptr, smem + OFF_H1, LD1B,
                                      g_WTh + W2T_OFF + (size_t)s * H2D * H1D,
                                      b2 + s * H2D, nullptr,
                                      smem, smem + OFF_H2, LD2B, nullptr);
        __syncthreads();
        // layer 3: h2 @ W3 -> celu -> fused dot W4 -> pd
        layer<H2D, H3D, false, true>(nullptr, nullptr, smem + OFF_H2, LD2B,
                                     g_WTh + W3T_OFF + (size_t)s * H3D * H2D,
                                     b3 + s * H3D, W4 + s * H3D,
                                     smem, nullptr, 0, pd);
        __syncthreads();

        // combine halves, mask pads, block reduce (rows 0..63 -> warps 0,1)
        float e = 0.0f;
        if (tid < MT) {
            if (base + tid < cnt) e = pd[tid * 2] + pd[tid * 2 + 1] + __ldg(b4 + s);
#pragma unroll
            for (int o = 16; o > 0; o >>= 1) e += __shfl_down_sync(0xffffffffu, e, o);
            if ((tid & 31) == 0) sred[tid >> 5] = e;
        }
        __syncthreads();
        if (tid == 0) g_partials[flat] = sred[0] + sred[1];
    } else {
        if (tid == 0) g_partials[flat] = 0.0f;
    }

    // ---- last CTA performs the deterministic global reduction ----
    __threadfence();
    if (tid == 0) {
        unsigned int t = atomicAdd(&g_ticket, 1u);
        is_last = (t == gridDim.x * gridDim.y - 1);
    }
    __syncthreads();
    if (is_last) {
        const int n = gridDim.x * gridDim.y;
        double acc = 0.0;
        for (int i = tid; i < n; i += 256) acc += (double)g_partials[i];
        sd[tid] = acc;
        __syncthreads();
#pragma unroll
        for (int o = 128; o > 0; o >>= 1) {
            if (tid < o) sd[tid] += sd[tid + o];
            __syncthreads();
        }
        if (tid == 0) {
            out[0] = (float)sd[0];
            g_ticket = 0;          // reset for next graph replay
        }
    }
}

// ---------------- weight transpose + RN fp16 (coalesced writes) -----------
__global__ void __launch_bounds__(256)
prep_kernel(const float* __restrict__ W1, const float* __restrict__ W2,
            const float* __restrict__ W3)
{
    int j = blockIdx.x * 256 + threadIdx.x;
    if (j < 4 * H1D * AEVD) {                  // W1T[sp][n][k] <- W1[sp][k][n]
        int sp = j / (H1D * AEVD), r = j % (H1D * AEVD);
        int n = r / AEVD, k = r % AEVD;
        g_WTh[W1T_OFF + j] = __float2half_rn(W1[(size_t)sp * AEVD * H1D + k * H1D + n]);
    }
    if (j < 4 * H2D * H1D) {
        int sp = j / (H2D * H1D), r = j % (H2D * H1D);
        int n = r / H1D, k = r % H1D;
        g_WTh[W2T_OFF + j] = __float2half_rn(W2[(size_t)sp * H1D * H2D + k * H2D + n]);
    }
    if (j < 4 * H3D * H2D) {
        int sp = j / (H3D * H2D), r = j % (H3D * H2D);
        int n = r / H2D, k = r % H2D;
        g_WTh[W3T_OFF + j] = __float2half_rn(W3[(size_t)sp * H2D * H3D + k * H3D + n]);
    }
}

extern "C" void kernel_launch(void* const* d_in, const int* in_sizes, int n_in,
                              void* d_out, int out_size)
{
    const float* aev = (const float*)d_in[0];
    const float* W1  = (const float*)d_in[1];
    const float* b1  = (const float*)d_in[2];
    const float* W2  = (const float*)d_in[3];
    const float* b2  = (const float*)d_in[4];
    const float* W3  = (const float*)d_in[5];
    const float* b3  = (const float*)d_in[6];
    const float* W4  = (const float*)d_in[7];
    const float* b4  = (const float*)d_in[8];
    const int* idx0  = (const int*)d_in[9];
    const int* idx1  = (const int*)d_in[10];
    const int* idx2  = (const int*)d_in[11];
    const int* idx3  = (const int*)d_in[12];

    int4 cnts;
    cnts.x = in_sizes[9];  cnts.y = in_sizes[10];
    cnts.z = in_sizes[11]; cnts.w = in_sizes[12];
    int maxc = cnts.x;
    if (cnts.y > maxc) maxc = cnts.y;
    if (cnts.z > maxc) maxc = cnts.z;
    if (cnts.w > maxc) maxc = cnts.w;
    int tiles = (maxc + MT - 1) / MT;

    prep_kernel<<<(4 * H1D * AEVD + 255) / 256, 256>>>(W1, W2, W3);

    cudaFuncSetAttribute(ani_kernel, cudaFuncAttributeMaxDynamicSharedMemorySize, SMEM_DYN);
    dim3 grid(tiles, 4);
    ani_kernel<<<grid, 256, SMEM_DYN>>>(aev, b1, b2, b3, W4, b4,
                                        idx0, idx1, idx2, idx3, cnts, (float*)d_out);
}